// round 17
// baseline (speedup 1.0000x reference)
#include <cuda_runtime.h>
#include <cuda_fp16.h>

// Radon forward projection, sm_103a — round 15.
// Exact-arithmetic micro-cuts on the binding issue/fma pipes and the
// coord->addr->LDS chain:
//  (1) frac fold: t' = i+2, magic const 8388607.5 -> fr = t' - fl (Sterbenz
//      exact), drops the +0.5 add.
//  (2) bits-IMAD addressing: magic float bits are 0x4B000000+n, so the two
//      "& 255" LOPs vanish; constant folds into a mod-2^32 byte offset.
//  (3) one f16x2 pack for (f0,f1) + half-lane broadcasts.
// Pair half2 accumulation, adaptive transpose, fp16x4 layout kept from R13.

#define STRIDE_E 131
#define SMEM_ELEMS (131 * STRIDE_E)           // 17161 entries (8 B each)
#define SMEM_BYTES (SMEM_ELEMS * 8 + 64)      // + trig table

#define N_ANG 285
#define N_DET 183
#define SINO  (N_ANG * N_DET)                 // 52155
#define NTHR  768

typedef unsigned long long u64;

__device__ __forceinline__ u64 pk2(float x, float y) {
    u64 u; asm("mov.b64 %0, {%1, %2};" : "=l"(u) : "f"(x), "f"(y)); return u;
}
__device__ __forceinline__ void upk2(u64 u, float& x, float& y) {
    asm("mov.b64 {%0, %1}, %2;" : "=f"(x), "=f"(y) : "l"(u));
}
__device__ __forceinline__ u64 fma2_(u64 a, u64 b, u64 c) {
    u64 d; asm("fma.rn.f32x2 %0, %1, %2, %3;" : "=l"(d) : "l"(a), "l"(b), "l"(c)); return d;
}
__device__ __forceinline__ u64 add2_(u64 a, u64 b) {
    u64 d; asm("add.rn.f32x2 %0, %1, %2;" : "=l"(d) : "l"(a), "l"(b)); return d;
}
__device__ __forceinline__ __half2 as_h2(unsigned u) {
    __half2 h; asm("mov.b32 %0, %1;" : "=r"(reinterpret_cast<unsigned&>(h)) : "r"(u)); return h;
}

// Byte-offset constant folding the magic-bits garbage (mod 2^32):
// raw*8 = 8*(131*n0+n1) + 1056*0x4B000000, want 8*(131*n0+n1) - 1056.
static __device__ __constant__ const unsigned kNothing = 0; // (placeholder)
#define OFFS_U32 ((unsigned)(0u - 1056u * 0x4B000001u))

__global__ __launch_bounds__(NTHR, 1)
void radon_fp_kernel(const float* __restrict__ x, float* __restrict__ out)
{
    extern __shared__ u64 imgs[];
    float2* trig = (float2*)(imgs + SMEM_ELEMS);

    const int tid = threadIdx.x;
    const int bg  = blockIdx.y;          // batch group: batches 4bg .. 4bg+3
    const int sub = tid / 192;           // which of 4 concurrent angles (0..3)
    const int det = tid % 192;

    // Transpose near-vertical quads (mid-angle in (pi/4, 3pi/4)).
    const float am = (4.0f * (float)blockIdx.x + 2.0f) * (1.0f / 285.0f);
    const bool T = (am > 0.25f) & (am < 0.75f);

    const float* gx0 = x + (4 * bg)     * 16384;
    const float* gx1 = x + (4 * bg + 1) * 16384;
    const float* gx2 = x + (4 * bg + 2) * 16384;
    const float* gx3 = x + (4 * bg + 3) * 16384;

    // Fill padded 4-batch fp16 image, optionally transposed.
    for (int e = tid; e < 131 * 131; e += NTHR) {
        int sr = e / 131;
        int sc = e - sr * 131;
        int pr = sr - 1, pc = sc - 1;
        bool in = ((unsigned)pr < 128u) & ((unsigned)pc < 128u);
        int gi = pr * 128 + pc;
        float v0 = in ? gx0[gi] : 0.0f;
        float v1 = in ? gx1[gi] : 0.0f;
        float v2 = in ? gx2[gi] : 0.0f;
        float v3 = in ? gx3[gi] : 0.0f;
        __half2 L = __floats2half2_rn(v0, v1);
        __half2 H = __floats2half2_rn(v2, v3);
        unsigned lo = reinterpret_cast<unsigned&>(L);
        unsigned hi = reinterpret_cast<unsigned&>(H);
        int dst = T ? (sc * STRIDE_E + sr) : (sr * STRIDE_E + sc);
        imgs[dst] = ((u64)hi << 32) | (u64)lo;
    }
    // Double-precision trig for this block's 4 angles.
    if (tid < 4) {
        int a = 4 * blockIdx.x + tid;
        if (a < N_ANG) {
            double sd, cd;
            sincospi((a + 0.5) / 285.0, &sd, &cd);
            trig[tid] = make_float2((float)sd, (float)cd);
        }
    }
    __syncthreads();

    // Constants (double-derived)
    const float RHOf = 28.284271247461902f;
    const float KD   = 0.47140452079103173f;        // DT/DX, DX = 0.3125
    const float t0c  = -28.284271247461902f + 0.5f * 0.14731391274719688f;
    const float scale = 0.012276159395599740f;      // DT/12
    const float s = fmaf((float)det + 0.5f, 2.0f * RHOf / 183.0f, -RHOf);

    const u64 BIGM2  = pk2( 8388607.5f,  8388607.5f);  // BIG - 0.5
    const u64 nBIG2  = pk2(-8388608.f,  -8388608.f);
    const u64 neg1   = pk2(-1.f, -1.f);
    const u64 one2   = pk2(1.f, 1.f);
    const char* imgc = (const char*)imgs;

    const int a = 4 * blockIdx.x + sub;
    if (det < N_DET && a < N_ANG) {
        float2 sc = trig[sub];
        float sn = sc.x, cs = sc.y;
        float d0r = KD * cs;
        float d1r = KD * sn;
        float c0r = fmaf(-s, sn, fmaf(t0c, cs, 20.0f)) * 3.2f - 0.5f;
        float c1r = fmaf( s, cs, fmaf(t0c, sn, 20.0f)) * 3.2f - 0.5f;
        // Axis swap for transposed storage
        float d0 = T ? d1r : d0r;
        float d1 = T ? d0r : d1r;
        float c0 = T ? c1r : c0r;
        float c1 = T ? c0r : c1r;

        // Valid window (content zero outside i in (-1, 128); safe to 129.49)
        const float LO = -0.999f, HI = 128.01f;
        float ra = (LO - c0) / d0, rb = (HI - c0) / d0;
        float klo = fmaxf(0.0f,  fminf(ra, rb));
        float khi = fminf(383.0f, fmaxf(ra, rb));
        ra = (LO - c1) / d1; rb = (HI - c1) / d1;
        klo = fmaxf(klo, fminf(ra, rb));
        khi = fminf(khi, fmaxf(ra, rb));
        int k0 = (int)ceilf(klo);
        int k1 = (int)floorf(khi);

        u64 d01  = pk2(d0, d1);
        u64 c01m = pk2(c0 + 2.0f, c1 + 2.0f);   // t' = i + 2
        u64 kf2  = pk2((float)k0, (float)k0);
        u64 accA = 0ull;                        // batches 0,1 (fp32 pair)
        u64 accB = 0ull;                        // batches 2,3

        // One bilinear sample at the given kf2 state -> half2 results.
        auto sample = [&](u64 kf2v, __half2& rA, __half2& rB) {
            u64 t01  = fma2_(kf2v, d01, c01m);       // i+2, both axes
            u64 y01  = add2_(t01, BIGM2);            // = round(i+1.5) + 2^23
            u64 fl01 = add2_(y01, nBIG2);            // = floor(i)+2 (exact)
            u64 fr01 = fma2_(fl01, neg1, t01);       // = frac(i), exact
            // Magic-float bits: y = 0x4B000000 + n -> feed words straight to IMAD.
            unsigned I0 = (unsigned)y01;
            unsigned I1 = (unsigned)(y01 >> 32);
            unsigned raw = I0 * 131u + I1;
            int delta = (int)(raw * 8u + OFFS_U32); // = 8*(131*n0+n1-132), small
            const uint2* p = (const uint2*)(imgc + delta);
            uint2 q00 = p[0];
            uint2 q01 = p[1];
            uint2 q10 = p[STRIDE_E];
            uint2 q11 = p[STRIDE_E + 1];
            float f0, f1; upk2(fr01, f0, f1);
            __half2 fh = __floats2half2_rn(f0, f1);  // one pack: {f0, f1}
            __half2 f0h = __half2half2(__low2half(fh));
            __half2 f1h = __half2half2(__high2half(fh));
            {
                __half2 a00 = as_h2(q00.x), a01 = as_h2(q01.x);
                __half2 a10 = as_h2(q10.x), a11 = as_h2(q11.x);
                __half2 m0h = __hfma2(f1h, __hsub2(a01, a00), a00);
                __half2 m1h = __hfma2(f1h, __hsub2(a11, a10), a10);
                rA = __hfma2(f0h, __hsub2(m1h, m0h), m0h);
            }
            {
                __half2 b00 = as_h2(q00.y), b01 = as_h2(q01.y);
                __half2 b10 = as_h2(q10.y), b11 = as_h2(q11.y);
                __half2 m0h = __hfma2(f1h, __hsub2(b01, b00), b00);
                __half2 m1h = __hfma2(f1h, __hsub2(b11, b10), b10);
                rB = __hfma2(f0h, __hsub2(m1h, m0h), m0h);
            }
        };

        int k = k0;
        #pragma unroll 2
        for (; k + 1 <= k1; k += 2) {
            __half2 rA0, rB0, rA1, rB1;
            sample(kf2, rA0, rB0);
            kf2 = add2_(kf2, one2);
            sample(kf2, rA1, rB1);
            kf2 = add2_(kf2, one2);
            __half2 sA = __hadd2(rA0, rA1);           // pairwise half sum
            __half2 sB = __hadd2(rB0, rB1);
            accA = add2_(accA, pk2(__low2float(sA), __high2float(sA)));
            accB = add2_(accB, pk2(__low2float(sB), __high2float(sB)));
        }
        if (k <= k1) {                                 // odd tail sample
            __half2 rA0, rB0;
            sample(kf2, rA0, rB0);
            accA = add2_(accA, pk2(__low2float(rA0), __high2float(rA0)));
            accB = add2_(accB, pk2(__low2float(rB0), __high2float(rB0)));
        }

        int ob = ((4 * bg) * N_ANG + a) * N_DET + det;
        float o0, o1, o2, o3;
        upk2(accA, o0, o1);
        upk2(accB, o2, o3);
        out[ob]            = o0 * scale;
        out[ob + SINO]     = o1 * scale;
        out[ob + 2 * SINO] = o2 * scale;
        out[ob + 3 * SINO] = o3 * scale;
    }
}

extern "C" void kernel_launch(void* const* d_in, const int* in_sizes, int n_in,
                              void* d_out, int out_size)
{
    const float* x = (const float*)d_in[0];
    float* out = (float*)d_out;

    static bool attr_set = false;
    if (!attr_set) {
        cudaFuncSetAttribute(radon_fp_kernel,
                             cudaFuncAttributeMaxDynamicSharedMemorySize, SMEM_BYTES);
        attr_set = true;
    }

    dim3 grid(72, 2);    // 72 angle-quads x 2 batch-groups = 144 blocks (1 wave)
    radon_fp_kernel<<<grid, NTHR, SMEM_BYTES>>>(x, out);
}